// round 9
// baseline (speedup 1.0000x reference)
#include <cuda_runtime.h>
#include <cstdint>

// ---------------------------------------------------------------------------
// RNN_arch_2: 16-step vanilla RNN, B=16384, D_IN=64, D_H=256, D_MID=64, D_OUT=4
// One block owns 64 batch rows; h lives in SMEM across all 16 steps.
// Round-2 changes: conflict-free W column mapping (j = tc + 32m), 512 threads
// (16 warps: 8 row-groups x 2 col-halves) for issue-latency hiding.
// Main GEMM uses packed fp32x2 FMA (FFMA2); W streamed L2->SMEM via cp.async.
// ---------------------------------------------------------------------------

#define T_STEPS 16
#define BATCH   16384
#define DIN     64
#define DH      256
#define DMID    64
#define DOUT    4
#define KTOT    (DIN + DH)      // 320

#define BT      64              // batch rows per block
#define NTH     512             // threads per block (16 warps)
#define KC      32              // K-chunk width
#define NCHUNK  (KTOT / KC)     // 10

// SMEM strides (floats); multiples of 4 keep 16B alignment for vector ops.
#define A_STRIDE    68          // A_s[k][row], 64 rows + pad
#define WC_STRIDE   36          // W chunk [j][kk]; lane stride 36 -> conflict-free LDS.128
#define MID_STRIDE  65

#define A_ELEMS     (KTOT * A_STRIDE)       // 21760
#define WBUF_ELEMS  (DH * WC_STRIDE)        // 9216
#define WAREA_ELEMS (2 * WBUF_ELEMS)        // 18432
#define MID_ELEMS   (BT * MID_STRIDE)       // 4160
#define WFC_ELEMS   (DOUT * DMID)           // 256

#define OFF_A    0
#define OFF_W    (OFF_A + A_ELEMS)
#define OFF_MID  (OFF_W + WAREA_ELEMS)
#define OFF_WFC  (OFF_MID + MID_ELEMS)
#define OFF_BFC  (OFF_WFC + WFC_ELEMS)
#define SMEM_FLOATS (OFF_BFC + DOUT)
#define SMEM_BYTES  (SMEM_FLOATS * 4)       // ~178 KB

// ----------------------------- PTX helpers ---------------------------------

__device__ __forceinline__ unsigned long long pack2(float lo, float hi) {
    unsigned long long r;
    asm("mov.b64 %0, {%1, %2};" : "=l"(r) : "f"(lo), "f"(hi));
    return r;
}
__device__ __forceinline__ void unpack2(unsigned long long p, float& lo, float& hi) {
    asm("mov.b64 {%0, %1}, %2;" : "=f"(lo), "=f"(hi) : "l"(p));
}
// Packed fp32x2 FMA: d = a * b + c  (two fp32 lanes per instruction -> FFMA2)
__device__ __forceinline__ unsigned long long fma2(unsigned long long a,
                                                   unsigned long long b,
                                                   unsigned long long c) {
    unsigned long long d;
    asm("fma.rn.f32x2 %0, %1, %2, %3;" : "=l"(d) : "l"(a), "l"(b), "l"(c));
    return d;
}

__device__ __forceinline__ void cp_async16(uint32_t smem_addr, const void* gptr) {
    asm volatile("cp.async.cg.shared.global [%0], [%1], 16;\n"
                 :: "r"(smem_addr), "l"(gptr));
}
#define CP_COMMIT() asm volatile("cp.async.commit_group;\n" ::: "memory")
#define CP_WAIT(n)  asm volatile("cp.async.wait_group %0;\n" :: "n"(n) : "memory")

// Fast, accurate tanh: 1 - 2/(e^{2x}+1).  Abs err ~1e-7; saturates correctly.
__device__ __forceinline__ float tanh_fast(float v) {
    float e = __expf(2.0f * v);
    return 1.0f - __fdividef(2.0f, e + 1.0f);
}

// ----------------------------- kernel --------------------------------------

__global__ void __launch_bounds__(NTH, 1)
rnn16_kernel(const float* __restrict__ x,      const float* __restrict__ hc1,
             const float* __restrict__ W_i2h,  const float* __restrict__ b_i2h,
             const float* __restrict__ W_h2h,  const float* __restrict__ b_h2h,
             const float* __restrict__ W_h2o,  const float* __restrict__ b_h2o,
             const float* __restrict__ W_fc,   const float* __restrict__ b_fc,
             float* __restrict__ out_seq,      float* __restrict__ h_final)
{
    extern __shared__ float smem[];
    float* A_s   = smem + OFF_A;    // [k][row], k in [0,320): 0..63 = x_t, 64.. = h
    float* Wbuf  = smem + OFF_W;    // 2 cp.async chunk buffers
    float* mid_s = smem + OFF_MID;  // [row][m]
    float* wfc_s = smem + OFF_WFC;
    float* bfc_s = smem + OFF_BFC;

    const int tid = threadIdx.x;
    const int tc  = tid & 31;       // lane
    const int tr  = tid >> 5;       // warp 0..15
    const int rg  = tr & 7;         // row group
    const int ch  = tr >> 3;        // column half (0: cols 0..127, 1: 128..255)
    const int r0  = rg * 8;         // this thread's 8 rows (4 fp32x2 pairs)
    const int jbase = tc + 128 * ch;  // cols: jbase + 32*m, m = 0..3
    const int rowbase = blockIdx.x * BT;

    // ---- W chunk streamer: chunk c covers global k in [c*32, c*32+32) -----
    auto issue_chunk = [&](int c, float* dst) {
        const int k0 = c * KC;
        const float* src;
        int rs;
        if (k0 < DIN) { src = W_i2h + k0; rs = DIN; }
        else          { src = W_h2h + (k0 - DIN); rs = DH; }
        #pragma unroll
        for (int i = 0; i < 4; ++i) {
            int e = tid + NTH * i;          // float4 index within chunk (2048)
            int j = e >> 3;                 // hidden col 0..255
            int q = e & 7;                  // k_local / 4
            uint32_t d = (uint32_t)__cvta_generic_to_shared(dst + j * WC_STRIDE + q * 4);
            cp_async16(d, src + (size_t)j * rs + q * 4);
        }
    };

    // Prefetch W chunk 0 of step 0 immediately.
    issue_chunk(0, Wbuf);
    CP_COMMIT();

    // fc weights + biases to smem
    if (tid < WFC_ELEMS) wfc_s[tid] = W_fc[tid];   // 4*64 = 256 floats
    if (tid < DOUT)      bfc_s[tid] = b_fc[tid];

    // Per-thread column biases (4 cols: j = jbase + 32*m)
    float bias[4];
    #pragma unroll
    for (int m = 0; m < 4; ++m)
        bias[m] = b_i2h[jbase + 32 * m] + b_h2h[jbase + 32 * m];

    const int   m0   = tc + 32 * ch;   // h2o column owned by this thread
    const float bmid = b_h2o[m0];

    // hc1 -> A_s h-region (transposed: [64+j][r])
    #pragma unroll
    for (int i = tid * 4; i < BT * DH; i += NTH * 4) {
        float4 v = *reinterpret_cast<const float4*>(&hc1[(size_t)rowbase * DH + i]);
        int r = i >> 8, j = i & 255;
        A_s[(DIN + j + 0) * A_STRIDE + r] = v.x;
        A_s[(DIN + j + 1) * A_STRIDE + r] = v.y;
        A_s[(DIN + j + 2) * A_STRIDE + r] = v.z;
        A_s[(DIN + j + 3) * A_STRIDE + r] = v.w;
    }
    // x_0 -> A_s x-region (transposed: [k][r])
    {
        const float* xp = x + (size_t)rowbase * DIN;
        #pragma unroll
        for (int i = tid * 4; i < BT * DIN; i += NTH * 4) {
            float4 v = *reinterpret_cast<const float4*>(&xp[i]);
            int r = i >> 6, k = i & 63;
            A_s[(k + 0) * A_STRIDE + r] = v.x;
            A_s[(k + 1) * A_STRIDE + r] = v.y;
            A_s[(k + 2) * A_STRIDE + r] = v.z;
            A_s[(k + 3) * A_STRIDE + r] = v.w;
        }
    }
    // (the first __syncthreads inside the chunk loop guards these writes)

    for (int t = 0; t < T_STEPS; ++t) {
        // ---- main GEMM: C[64 x 256] over K = 320 ---------------------------
        // acc[m*4 + rp] packs rows (r0+2rp, r0+2rp+1) for col jbase+32m.
        unsigned long long acc[16];
        #pragma unroll
        for (int m = 0; m < 4; ++m)
            #pragma unroll
            for (int rp = 0; rp < 4; ++rp)
                acc[m * 4 + rp] = pack2(bias[m], bias[m]);

        #pragma unroll 1
        for (int c = 0; c < NCHUNK; ++c) {
            if (c + 1 < NCHUNK) {
                issue_chunk(c + 1, Wbuf + ((c + 1) & 1) * WBUF_ELEMS);
                CP_COMMIT();
                CP_WAIT(1);
            } else {
                CP_WAIT(0);
            }
            __syncthreads();  // chunk c visible; also guards A_s writes

            const float* wb = Wbuf + (c & 1) * WBUF_ELEMS;
            const int kbase = c * KC;
            #pragma unroll
            for (int kk = 0; kk < KC; kk += 4) {
                // 4 cols x 4 k of W; lane stride 36 floats -> conflict-free
                float4 wv[4];
                #pragma unroll
                for (int m = 0; m < 4; ++m)
                    wv[m] = *reinterpret_cast<const float4*>(
                        &wb[(jbase + 32 * m) * WC_STRIDE + kk]);
                #pragma unroll
                for (int dk = 0; dk < 4; ++dk) {
                    const float* ap = &A_s[(kbase + kk + dk) * A_STRIDE + r0];
                    ulonglong2 pA = *reinterpret_cast<const ulonglong2*>(ap);
                    ulonglong2 pB = *reinterpret_cast<const ulonglong2*>(ap + 4);
                    unsigned long long a2[4] = { pA.x, pA.y, pB.x, pB.y };
                    #pragma unroll
                    for (int m = 0; m < 4; ++m) {
                        float w = reinterpret_cast<const float*>(&wv[m])[dk];
                        unsigned long long w2 = pack2(w, w);
                        #pragma unroll
                        for (int rp = 0; rp < 4; ++rp)
                            acc[m * 4 + rp] = fma2(a2[rp], w2, acc[m * 4 + rp]);
                    }
                }
            }
            __syncthreads();  // done reading buf[c&1] before it is re-filled
        }

        // ---- h_new = tanh(C) -> A_s h-region -------------------------------
        #pragma unroll
        for (int m = 0; m < 4; ++m) {
            int j = jbase + 32 * m;
            #pragma unroll
            for (int rp = 0; rp < 4; ++rp) {
                float lo, hi;
                unpack2(acc[m * 4 + rp], lo, hi);
                float2 h2;
                h2.x = tanh_fast(lo);
                h2.y = tanh_fast(hi);
                *reinterpret_cast<float2*>(&A_s[(DIN + j) * A_STRIDE + r0 + 2 * rp]) = h2;
            }
        }
        __syncthreads();

        // Prefetch next step's first W chunk now; the double-buffer region is
        // idle for the rest of this step.
        if (t + 1 < T_STEPS) {
            issue_chunk(0, Wbuf);
            CP_COMMIT();
        }

        // ---- h2o GEMM: mid[64 x 64] = tanh(h_new @ W_h2o^T + b) ------------
        // Each thread: 1 mid column (m0) x 8 rows. W_h2o row m0 from L1
        // (rows repeat across the 8 row-group warps -> L1 hits).
        {
            unsigned long long a0[4];
            #pragma unroll
            for (int rp = 0; rp < 4; ++rp) a0[rp] = pack2(bmid, bmid);
            const float4* wp = reinterpret_cast<const float4*>(W_h2o + (size_t)m0 * DH);
            #pragma unroll 2
            for (int k = 0; k < DH; k += 4) {
                float4 w = __ldg(&wp[k >> 2]);
                #pragma unroll
                for (int dk = 0; dk < 4; ++dk) {
                    const float* ap = &A_s[(DIN + k + dk) * A_STRIDE + r0];
                    ulonglong2 pA = *reinterpret_cast<const ulonglong2*>(ap);
                    ulonglong2 pB = *reinterpret_cast<const ulonglong2*>(ap + 4);
                    unsigned long long a2[4] = { pA.x, pA.y, pB.x, pB.y };
                    float f = reinterpret_cast<const float*>(&w)[dk];
                    unsigned long long w2 = pack2(f, f);
                    #pragma unroll
                    for (int rp = 0; rp < 4; ++rp)
                        a0[rp] = fma2(a2[rp], w2, a0[rp]);
                }
            }
            #pragma unroll
            for (int rp = 0; rp < 4; ++rp) {
                float lo, hi;
                unpack2(a0[rp], lo, hi);
                mid_s[(r0 + 2 * rp + 0) * MID_STRIDE + m0] = tanh_fast(lo);
                mid_s[(r0 + 2 * rp + 1) * MID_STRIDE + m0] = tanh_fast(hi);
            }
        }
        __syncthreads();

        // ---- fc: out[r][o] = mid[r] @ W_fc[o]^T + b_fc ---------------------
        if (tid < BT * DOUT) {
            int r = tid >> 2, o = tid & 3;
            float accf = bfc_s[o];
            #pragma unroll
            for (int m = 0; m < DMID; ++m)
                accf = fmaf(mid_s[r * MID_STRIDE + m], wfc_s[o * DMID + m], accf);
            out_seq[((size_t)t * BATCH + rowbase + r) * DOUT + o] = accf;
        }

        // ---- load x_{t+1} into A_s x-region (no reader until next c-loop) --
        if (t + 1 < T_STEPS) {
            const float* xp = x + (size_t)(t + 1) * BATCH * DIN + (size_t)rowbase * DIN;
            #pragma unroll
            for (int i = tid * 4; i < BT * DIN; i += NTH * 4) {
                float4 v = *reinterpret_cast<const float4*>(&xp[i]);
                int r = i >> 6, k = i & 63;
                A_s[(k + 0) * A_STRIDE + r] = v.x;
                A_s[(k + 1) * A_STRIDE + r] = v.y;
                A_s[(k + 2) * A_STRIDE + r] = v.z;
                A_s[(k + 3) * A_STRIDE + r] = v.w;
            }
        }
        // next iteration's first in-chunk-loop __syncthreads guards these
    }

    // ---- h_final: copy A_s h-region to gmem (coalesced) --------------------
    __syncthreads();
    #pragma unroll
    for (int i = tid * 4; i < BT * DH; i += NTH * 4) {
        int r = i >> 8, j = i & 255;
        float4 v;
        v.x = A_s[(DIN + j + 0) * A_STRIDE + r];
        v.y = A_s[(DIN + j + 1) * A_STRIDE + r];
        v.z = A_s[(DIN + j + 2) * A_STRIDE + r];
        v.w = A_s[(DIN + j + 3) * A_STRIDE + r];
        *reinterpret_cast<float4*>(&h_final[(size_t)(rowbase + r) * DH + j]) = v;
    }
}

// ----------------------------- launch wrapper -------------------------------

extern "C" void kernel_launch(void* const* d_in, const int* in_sizes, int n_in,
                              void* d_out, int out_size) {
    const float* x     = (const float*)d_in[0];
    const float* hc1   = (const float*)d_in[1];
    const float* W_i2h = (const float*)d_in[2];
    const float* b_i2h = (const float*)d_in[3];
    const float* W_h2h = (const float*)d_in[4];
    const float* b_h2h = (const float*)d_in[5];
    const float* W_h2o = (const float*)d_in[6];
    const float* b_h2o = (const float*)d_in[7];
    const float* W_fc  = (const float*)d_in[8];
    const float* b_fc  = (const float*)d_in[9];

    float* out = (float*)d_out;
    float* h_final = out + (size_t)T_STEPS * BATCH * DOUT;  // out_seq, then h_final

    cudaFuncSetAttribute(rnn16_kernel,
                         cudaFuncAttributeMaxDynamicSharedMemorySize,
                         (int)SMEM_BYTES);

    rnn16_kernel<<<BATCH / BT, NTH, SMEM_BYTES>>>(
        x, hc1, W_i2h, b_i2h, W_h2h, b_h2h, W_h2o, b_h2o, W_fc, b_fc,
        out, h_final);
}

// round 11
// speedup vs baseline: 1.0011x; 1.0011x over previous
#include <cuda_runtime.h>
#include <cstdint>

// ---------------------------------------------------------------------------
// RNN_arch_2: 16-step vanilla RNN, B=16384, D_IN=64, D_H=256, D_MID=64, D_OUT=4
// One block owns 64 batch rows; h lives in SMEM across all 16 steps.
// Round-2 changes: conflict-free W column mapping (j = tc + 32m), 512 threads
// (16 warps: 8 row-groups x 2 col-halves) for issue-latency hiding.
// Main GEMM uses packed fp32x2 FMA (FFMA2); W streamed L2->SMEM via cp.async.
// ---------------------------------------------------------------------------

#define T_STEPS 16
#define BATCH   16384
#define DIN     64
#define DH      256
#define DMID    64
#define DOUT    4
#define KTOT    (DIN + DH)      // 320

#define BT      64              // batch rows per block
#define NTH     512             // threads per block (16 warps)
#define KC      32              // K-chunk width
#define NCHUNK  (KTOT / KC)     // 10

// SMEM strides (floats); multiples of 4 keep 16B alignment for vector ops.
#define A_STRIDE    68          // A_s[k][row], 64 rows + pad
#define WC_STRIDE   36          // W chunk [j][kk]; lane stride 36 -> conflict-free LDS.128
#define MID_STRIDE  65

#define A_ELEMS     (KTOT * A_STRIDE)       // 21760
#define WBUF_ELEMS  (DH * WC_STRIDE)        // 9216
#define WAREA_ELEMS (2 * WBUF_ELEMS)        // 18432
#define MID_ELEMS   (BT * MID_STRIDE)       // 4160
#define WFC_ELEMS   (DOUT * DMID)           // 256

#define OFF_A    0
#define OFF_W    (OFF_A + A_ELEMS)
#define OFF_MID  (OFF_W + WAREA_ELEMS)
#define OFF_WFC  (OFF_MID + MID_ELEMS)
#define OFF_BFC  (OFF_WFC + WFC_ELEMS)
#define SMEM_FLOATS (OFF_BFC + DOUT)
#define SMEM_BYTES  (SMEM_FLOATS * 4)       // ~178 KB

// ----------------------------- PTX helpers ---------------------------------

__device__ __forceinline__ unsigned long long pack2(float lo, float hi) {
    unsigned long long r;
    asm("mov.b64 %0, {%1, %2};" : "=l"(r) : "f"(lo), "f"(hi));
    return r;
}
__device__ __forceinline__ void unpack2(unsigned long long p, float& lo, float& hi) {
    asm("mov.b64 {%0, %1}, %2;" : "=f"(lo), "=f"(hi) : "l"(p));
}
// Packed fp32x2 FMA: d = a * b + c  (two fp32 lanes per instruction -> FFMA2)
__device__ __forceinline__ unsigned long long fma2(unsigned long long a,
                                                   unsigned long long b,
                                                   unsigned long long c) {
    unsigned long long d;
    asm("fma.rn.f32x2 %0, %1, %2, %3;" : "=l"(d) : "l"(a), "l"(b), "l"(c));
    return d;
}

__device__ __forceinline__ void cp_async16(uint32_t smem_addr, const void* gptr) {
    asm volatile("cp.async.cg.shared.global [%0], [%1], 16;\n"
                 :: "r"(smem_addr), "l"(gptr));
}
#define CP_COMMIT() asm volatile("cp.async.commit_group;\n" ::: "memory")
#define CP_WAIT(n)  asm volatile("cp.async.wait_group %0;\n" :: "n"(n) : "memory")

// Fast, accurate tanh: 1 - 2/(e^{2x}+1).  Abs err ~1e-7; saturates correctly.
__device__ __forceinline__ float tanh_fast(float v) {
    float e = __expf(2.0f * v);
    return 1.0f - __fdividef(2.0f, e + 1.0f);
}

// ----------------------------- kernel --------------------------------------

__global__ void __launch_bounds__(NTH, 1)
rnn16_kernel(const float* __restrict__ x,      const float* __restrict__ hc1,
             const float* __restrict__ W_i2h,  const float* __restrict__ b_i2h,
             const float* __restrict__ W_h2h,  const float* __restrict__ b_h2h,
             const float* __restrict__ W_h2o,  const float* __restrict__ b_h2o,
             const float* __restrict__ W_fc,   const float* __restrict__ b_fc,
             float* __restrict__ out_seq,      float* __restrict__ h_final)
{
    extern __shared__ float smem[];
    float* A_s   = smem + OFF_A;    // [k][row], k in [0,320): 0..63 = x_t, 64.. = h
    float* Wbuf  = smem + OFF_W;    // 2 cp.async chunk buffers
    float* mid_s = smem + OFF_MID;  // [row][m]
    float* wfc_s = smem + OFF_WFC;
    float* bfc_s = smem + OFF_BFC;

    const int tid = threadIdx.x;
    const int tc  = tid & 31;       // lane
    const int tr  = tid >> 5;       // warp 0..15
    const int rg  = tr & 7;         // row group
    const int ch  = tr >> 3;        // column half (0: cols 0..127, 1: 128..255)
    const int r0  = rg * 8;         // this thread's 8 rows (4 fp32x2 pairs)
    const int jbase = tc + 128 * ch;  // cols: jbase + 32*m, m = 0..3
    const int rowbase = blockIdx.x * BT;

    // ---- W chunk streamer: chunk c covers global k in [c*32, c*32+32) -----
    auto issue_chunk = [&](int c, float* dst) {
        const int k0 = c * KC;
        const float* src;
        int rs;
        if (k0 < DIN) { src = W_i2h + k0; rs = DIN; }
        else          { src = W_h2h + (k0 - DIN); rs = DH; }
        #pragma unroll
        for (int i = 0; i < 4; ++i) {
            int e = tid + NTH * i;          // float4 index within chunk (2048)
            int j = e >> 3;                 // hidden col 0..255
            int q = e & 7;                  // k_local / 4
            uint32_t d = (uint32_t)__cvta_generic_to_shared(dst + j * WC_STRIDE + q * 4);
            cp_async16(d, src + (size_t)j * rs + q * 4);
        }
    };

    // Prefetch W chunk 0 of step 0 immediately.
    issue_chunk(0, Wbuf);
    CP_COMMIT();

    // fc weights + biases to smem
    if (tid < WFC_ELEMS) wfc_s[tid] = W_fc[tid];   // 4*64 = 256 floats
    if (tid < DOUT)      bfc_s[tid] = b_fc[tid];

    // Per-thread column biases (4 cols: j = jbase + 32*m)
    float bias[4];
    #pragma unroll
    for (int m = 0; m < 4; ++m)
        bias[m] = b_i2h[jbase + 32 * m] + b_h2h[jbase + 32 * m];

    const int   m0   = tc + 32 * ch;   // h2o column owned by this thread
    const float bmid = b_h2o[m0];

    // hc1 -> A_s h-region (transposed: [64+j][r])
    #pragma unroll
    for (int i = tid * 4; i < BT * DH; i += NTH * 4) {
        float4 v = *reinterpret_cast<const float4*>(&hc1[(size_t)rowbase * DH + i]);
        int r = i >> 8, j = i & 255;
        A_s[(DIN + j + 0) * A_STRIDE + r] = v.x;
        A_s[(DIN + j + 1) * A_STRIDE + r] = v.y;
        A_s[(DIN + j + 2) * A_STRIDE + r] = v.z;
        A_s[(DIN + j + 3) * A_STRIDE + r] = v.w;
    }
    // x_0 -> A_s x-region (transposed: [k][r])
    {
        const float* xp = x + (size_t)rowbase * DIN;
        #pragma unroll
        for (int i = tid * 4; i < BT * DIN; i += NTH * 4) {
            float4 v = *reinterpret_cast<const float4*>(&xp[i]);
            int r = i >> 6, k = i & 63;
            A_s[(k + 0) * A_STRIDE + r] = v.x;
            A_s[(k + 1) * A_STRIDE + r] = v.y;
            A_s[(k + 2) * A_STRIDE + r] = v.z;
            A_s[(k + 3) * A_STRIDE + r] = v.w;
        }
    }
    // (the first __syncthreads inside the chunk loop guards these writes)

    for (int t = 0; t < T_STEPS; ++t) {
        // ---- main GEMM: C[64 x 256] over K = 320 ---------------------------
        // acc[m*4 + rp] packs rows (r0+2rp, r0+2rp+1) for col jbase+32m.
        unsigned long long acc[16];
        #pragma unroll
        for (int m = 0; m < 4; ++m)
            #pragma unroll
            for (int rp = 0; rp < 4; ++rp)
                acc[m * 4 + rp] = pack2(bias[m], bias[m]);

        #pragma unroll 1
        for (int c = 0; c < NCHUNK; ++c) {
            if (c + 1 < NCHUNK) {
                issue_chunk(c + 1, Wbuf + ((c + 1) & 1) * WBUF_ELEMS);
                CP_COMMIT();
                CP_WAIT(1);
            } else {
                CP_WAIT(0);
            }
            __syncthreads();  // chunk c visible; also guards A_s writes

            const float* wb = Wbuf + (c & 1) * WBUF_ELEMS;
            const int kbase = c * KC;
            #pragma unroll
            for (int kk = 0; kk < KC; kk += 4) {
                // 4 cols x 4 k of W; lane stride 36 floats -> conflict-free
                float4 wv[4];
                #pragma unroll
                for (int m = 0; m < 4; ++m)
                    wv[m] = *reinterpret_cast<const float4*>(
                        &wb[(jbase + 32 * m) * WC_STRIDE + kk]);
                #pragma unroll
                for (int dk = 0; dk < 4; ++dk) {
                    const float* ap = &A_s[(kbase + kk + dk) * A_STRIDE + r0];
                    ulonglong2 pA = *reinterpret_cast<const ulonglong2*>(ap);
                    ulonglong2 pB = *reinterpret_cast<const ulonglong2*>(ap + 4);
                    unsigned long long a2[4] = { pA.x, pA.y, pB.x, pB.y };
                    #pragma unroll
                    for (int m = 0; m < 4; ++m) {
                        float w = reinterpret_cast<const float*>(&wv[m])[dk];
                        unsigned long long w2 = pack2(w, w);
                        #pragma unroll
                        for (int rp = 0; rp < 4; ++rp)
                            acc[m * 4 + rp] = fma2(a2[rp], w2, acc[m * 4 + rp]);
                    }
                }
            }
            __syncthreads();  // done reading buf[c&1] before it is re-filled
        }

        // ---- h_new = tanh(C) -> A_s h-region -------------------------------
        #pragma unroll
        for (int m = 0; m < 4; ++m) {
            int j = jbase + 32 * m;
            #pragma unroll
            for (int rp = 0; rp < 4; ++rp) {
                float lo, hi;
                unpack2(acc[m * 4 + rp], lo, hi);
                float2 h2;
                h2.x = tanh_fast(lo);
                h2.y = tanh_fast(hi);
                *reinterpret_cast<float2*>(&A_s[(DIN + j) * A_STRIDE + r0 + 2 * rp]) = h2;
            }
        }
        __syncthreads();

        // Prefetch next step's first W chunk now; the double-buffer region is
        // idle for the rest of this step.
        if (t + 1 < T_STEPS) {
            issue_chunk(0, Wbuf);
            CP_COMMIT();
        }

        // ---- h2o GEMM: mid[64 x 64] = tanh(h_new @ W_h2o^T + b) ------------
        // Each thread: 1 mid column (m0) x 8 rows. W_h2o row m0 from L1
        // (rows repeat across the 8 row-group warps -> L1 hits).
        {
            unsigned long long a0[4];
            #pragma unroll
            for (int rp = 0; rp < 4; ++rp) a0[rp] = pack2(bmid, bmid);
            const float4* wp = reinterpret_cast<const float4*>(W_h2o + (size_t)m0 * DH);
            #pragma unroll 2
            for (int k = 0; k < DH; k += 4) {
                float4 w = __ldg(&wp[k >> 2]);
                #pragma unroll
                for (int dk = 0; dk < 4; ++dk) {
                    const float* ap = &A_s[(DIN + k + dk) * A_STRIDE + r0];
                    ulonglong2 pA = *reinterpret_cast<const ulonglong2*>(ap);
                    ulonglong2 pB = *reinterpret_cast<const ulonglong2*>(ap + 4);
                    unsigned long long a2[4] = { pA.x, pA.y, pB.x, pB.y };
                    float f = reinterpret_cast<const float*>(&w)[dk];
                    unsigned long long w2 = pack2(f, f);
                    #pragma unroll
                    for (int rp = 0; rp < 4; ++rp)
                        a0[rp] = fma2(a2[rp], w2, a0[rp]);
                }
            }
            #pragma unroll
            for (int rp = 0; rp < 4; ++rp) {
                float lo, hi;
                unpack2(a0[rp], lo, hi);
                mid_s[(r0 + 2 * rp + 0) * MID_STRIDE + m0] = tanh_fast(lo);
                mid_s[(r0 + 2 * rp + 1) * MID_STRIDE + m0] = tanh_fast(hi);
            }
        }
        __syncthreads();

        // ---- fc: out[r][o] = mid[r] @ W_fc[o]^T + b_fc ---------------------
        if (tid < BT * DOUT) {
            int r = tid >> 2, o = tid & 3;
            float accf = bfc_s[o];
            #pragma unroll
            for (int m = 0; m < DMID; ++m)
                accf = fmaf(mid_s[r * MID_STRIDE + m], wfc_s[o * DMID + m], accf);
            out_seq[((size_t)t * BATCH + rowbase + r) * DOUT + o] = accf;
        }

        // ---- load x_{t+1} into A_s x-region (no reader until next c-loop) --
        if (t + 1 < T_STEPS) {
            const float* xp = x + (size_t)(t + 1) * BATCH * DIN + (size_t)rowbase * DIN;
            #pragma unroll
            for (int i = tid * 4; i < BT * DIN; i += NTH * 4) {
                float4 v = *reinterpret_cast<const float4*>(&xp[i]);
                int r = i >> 6, k = i & 63;
                A_s[(k + 0) * A_STRIDE + r] = v.x;
                A_s[(k + 1) * A_STRIDE + r] = v.y;
                A_s[(k + 2) * A_STRIDE + r] = v.z;
                A_s[(k + 3) * A_STRIDE + r] = v.w;
            }
        }
        // next iteration's first in-chunk-loop __syncthreads guards these
    }

    // ---- h_final: copy A_s h-region to gmem (coalesced) --------------------
    __syncthreads();
    #pragma unroll
    for (int i = tid * 4; i < BT * DH; i += NTH * 4) {
        int r = i >> 8, j = i & 255;
        float4 v;
        v.x = A_s[(DIN + j + 0) * A_STRIDE + r];
        v.y = A_s[(DIN + j + 1) * A_STRIDE + r];
        v.z = A_s[(DIN + j + 2) * A_STRIDE + r];
        v.w = A_s[(DIN + j + 3) * A_STRIDE + r];
        *reinterpret_cast<float4*>(&h_final[(size_t)(rowbase + r) * DH + j]) = v;
    }
}

// ----------------------------- launch wrapper -------------------------------

extern "C" void kernel_launch(void* const* d_in, const int* in_sizes, int n_in,
                              void* d_out, int out_size) {
    const float* x     = (const float*)d_in[0];
    const float* hc1   = (const float*)d_in[1];
    const float* W_i2h = (const float*)d_in[2];
    const float* b_i2h = (const float*)d_in[3];
    const float* W_h2h = (const float*)d_in[4];
    const float* b_h2h = (const float*)d_in[5];
    const float* W_h2o = (const float*)d_in[6];
    const float* b_h2o = (const float*)d_in[7];
    const float* W_fc  = (const float*)d_in[8];
    const float* b_fc  = (const float*)d_in[9];

    float* out = (float*)d_out;
    float* h_final = out + (size_t)T_STEPS * BATCH * DOUT;  // out_seq, then h_final

    cudaFuncSetAttribute(rnn16_kernel,
                         cudaFuncAttributeMaxDynamicSharedMemorySize,
                         (int)SMEM_BYTES);

    rnn16_kernel<<<BATCH / BT, NTH, SMEM_BYTES>>>(
        x, hc1, W_i2h, b_i2h, W_h2h, b_h2h, W_h2o, b_h2o, W_fc, b_fc,
        out, h_final);
}

// round 14
// speedup vs baseline: 3.1687x; 3.1651x over previous
#include <cuda_runtime.h>
#include <cuda_bf16.h>
#include <cstdint>

#define T_STEPS 16
#define BATCH   16384
#define DIN     64
#define DH      256
#define DMID    64
#define DOUT    4
#define BT      128
#define NTH     512

// SMEM layout (bytes)
#define OFF_A   2560                    // cs consts before it (640 floats)
#define AREG    81920                   // one A copy: 8 mt * 20 ks * 512B
#define OFF_AL  (OFF_A + AREG)          // 84480
#define OFF_B   (OFF_AL + AREG)         // 166400 (two 32KB chunk buffers)
#define OFF_MID (OFF_B + 30720)         // mid scratch 128*66*4 = 33792
#define SMEM_TOTAL (OFF_B + 65536)      // 231936

// Weights in MMA-fragment order (bf16 hi/lo). B: [ks 0..19][nt 0..31][128 bf16]
__device__ __nv_bfloat16 g_Bhi[20*32*128];
__device__ __nv_bfloat16 g_Blo[20*32*128];
__device__ __nv_bfloat16 g_Ohi[16*8*128];
__device__ __nv_bfloat16 g_Olo[16*8*128];

__device__ __forceinline__ void split2(float a, float b, uint32_t& hi, uint32_t& lo){
    __nv_bfloat16 ha=__float2bfloat16(a), hb=__float2bfloat16(b);
    float ra=a-__bfloat162float(ha), rb=b-__bfloat162float(hb);
    __nv_bfloat16 la=__float2bfloat16(ra), lb=__float2bfloat16(rb);
    hi = ((uint32_t)(*(uint16_t*)&hb) << 16) | *(uint16_t*)&ha;
    lo = ((uint32_t)(*(uint16_t*)&lb) << 16) | *(uint16_t*)&la;
}
__device__ __forceinline__ void cp16(uint32_t d, const void* s){
    asm volatile("cp.async.cg.shared.global [%0], [%1], 16;"::"r"(d),"l"(s));
}
#define CP_COMMIT() asm volatile("cp.async.commit_group;":::"memory")
#define CP_WAIT1()  asm volatile("cp.async.wait_group 1;":::"memory")
#define CP_WAIT0()  asm volatile("cp.async.wait_group 0;":::"memory")

__device__ __forceinline__ void mma16816(float* c, uint4 a, uint2 b){
    asm("mma.sync.aligned.m16n8k16.row.col.f32.bf16.bf16.f32 "
        "{%0,%1,%2,%3},{%4,%5,%6,%7},{%8,%9},{%0,%1,%2,%3};"
        : "+f"(c[0]),"+f"(c[1]),"+f"(c[2]),"+f"(c[3])
        : "r"(a.x),"r"(a.y),"r"(a.z),"r"(a.w),"r"(b.x),"r"(b.y));
}
__device__ __forceinline__ float tanh_fast(float v){
    float e=__expf(2.0f*v); return 1.0f-__fdividef(2.0f,e+1.0f);
}

// ---- prep: split weights to bf16 hi/lo in fragment order ----
__global__ void prep(const float* __restrict__ Wi, const float* __restrict__ Wh,
                     const float* __restrict__ Wo){
    int i=blockIdx.x*blockDim.x+threadIdx.x;
    if(i < 256*320){
        int j=i/320, k=i%320;
        float v=(k<DIN)? Wi[j*DIN+k] : Wh[j*DH+(k-DIN)];
        __nv_bfloat16 h=__float2bfloat16(v);
        __nv_bfloat16 l=__float2bfloat16(v-__bfloat162float(h));
        uint32_t a=((k>>4)*32+(j>>3))*128 + ((j&7)*4+((k&7)>>1))*4
                 + ((k&15)>>3)*2 + (k&1);
        g_Bhi[a]=h; g_Blo[a]=l;
    } else if(i < 256*320 + 64*256){
        int i2=i-256*320, j=i2/256, k=i2%256;
        float v=Wo[j*DH+k];
        __nv_bfloat16 h=__float2bfloat16(v);
        __nv_bfloat16 l=__float2bfloat16(v-__bfloat162float(h));
        uint32_t a=((k>>4)*8+(j>>3))*128 + ((j&7)*4+((k&7)>>1))*4
                 + ((k&15)>>3)*2 + (k&1);
        g_Ohi[a]=h; g_Olo[a]=l;
    }
}

// ------------------------------- main kernel -------------------------------
__global__ void __launch_bounds__(NTH,1)
rnn_mma(const float* __restrict__ x,     const float* __restrict__ hc1,
        const float* __restrict__ b_i2h, const float* __restrict__ b_h2h,
        const float* __restrict__ b_h2o, const float* __restrict__ W_fc,
        const float* __restrict__ b_fc,
        float* __restrict__ out_seq,     float* __restrict__ h_final)
{
    extern __shared__ __align__(128) char sm[];
    float* cs=(float*)sm;                       // [0,256) bias, [256,320) b_h2o,
    char* Ahi=sm+OFF_A; char* Alo=sm+OFF_AL;    // [320,324) b_fc, [324,580) W_fc
    char* Bb =sm+OFF_B;
    const int tid=threadIdx.x, lane=tid&31, w=tid>>5;
    const int mtp=w>>2, ncg=w&3;
    const int rowbase=blockIdx.x*BT;
    const uint32_t sbB=(uint32_t)__cvta_generic_to_shared(Bb);

    if(tid<DH)   cs[tid]    =b_i2h[tid]+b_h2h[tid];
    if(tid<DMID) cs[256+tid]=b_h2o[tid];
    if(tid<DOUT) cs[320+tid]=b_fc[tid];
    if(tid<256)  cs[324+tid]=W_fc[tid];

    // hc1 -> A frag h-region (ks 4..19)
    #pragma unroll 4
    for(int i=0;i<32;++i){
        int wi=tid+NTH*i;                       // [0,16384)
        int mt=wi>>11, ks=(wi>>7)&15, ln=(wi>>2)&31, rg=wi&3;
        int row=mt*16+(rg&1)*8+(ln>>2);
        int k  =ks*16+(rg>>1)*8+(ln&3)*2;
        float2 v=*(const float2*)&hc1[(size_t)(rowbase+row)*DH+k];
        uint32_t hw,lw; split2(v.x,v.y,hw,lw);
        uint32_t off=(uint32_t)((mt*20+4+ks)*512+ln*16+rg*4);
        *(uint32_t*)(Ahi+off)=hw; *(uint32_t*)(Alo+off)=lw;
    }

    for(int t=0;t<T_STEPS;++t){
        // ---- stage x_t: linear 32KB -> Bb, then convert to A frags ks0..3 --
        {
            const float* xp=x+((size_t)t*BATCH+rowbase)*DIN;
            #pragma unroll
            for(int i=0;i<4;++i) cp16(sbB+(uint32_t)((tid+NTH*i)*16), xp+(tid+NTH*i)*4);
            CP_COMMIT(); CP_WAIT0(); __syncthreads();
            const float* xs=(const float*)Bb;
            #pragma unroll
            for(int i=0;i<8;++i){
                int wi=tid+NTH*i;               // [0,4096)
                int mt=wi>>9, ks=(wi>>7)&3, ln=(wi>>2)&31, rg=wi&3;
                int row=mt*16+(rg&1)*8+(ln>>2);
                int k  =ks*16+(rg>>1)*8+(ln&3)*2;
                float2 v=*(const float2*)&xs[row*DIN+k];
                uint32_t hw,lw; split2(v.x,v.y,hw,lw);
                uint32_t off=(uint32_t)((mt*20+ks)*512+ln*16+rg*4);
                *(uint32_t*)(Ahi+off)=hw; *(uint32_t*)(Alo+off)=lw;
            }
            __syncthreads();
        }

        // ---- main GEMM: C[128x256] over K=320, 3 bf16 passes ---------------
        float acc[16][4];
        #pragma unroll
        for(int nt=0;nt<8;++nt){
            int col=ncg*64+nt*8+(lane&3)*2;
            float b0=cs[col], b1=cs[col+1];
            acc[nt][0]=b0; acc[nt][1]=b1; acc[nt][2]=b0; acc[nt][3]=b1;
            acc[8+nt][0]=b0; acc[8+nt][1]=b1; acc[8+nt][2]=b0; acc[8+nt][3]=b1;
        }
        #pragma unroll 1
        for(int p=0;p<3;++p){
            const char* Ab=(p<2)?Ahi:Alo;
            const __nv_bfloat16* src=(p==1)?g_Blo:g_Bhi;
            #pragma unroll
            for(int c0=0;c0<2;++c0){
                const char* s=(const char*)src + c0*32768;
                #pragma unroll
                for(int i=0;i<4;++i)
                    cp16(sbB+(uint32_t)(c0*32768+(tid+NTH*i)*16), s+(tid+NTH*i)*16);
                CP_COMMIT();
            }
            #pragma unroll 1
            for(int c=0;c<5;++c){
                if(c<4){ CP_WAIT1(); } else { CP_WAIT0(); }
                __syncthreads();
                const char* bb=Bb+(c&1)*32768;
                #pragma unroll
                for(int ksl=0;ksl<4;++ksl){
                    int ks=c*4+ksl;
                    uint4 a0=*(const uint4*)(Ab+((2*mtp  )*20+ks)*512+lane*16);
                    uint4 a1=*(const uint4*)(Ab+((2*mtp+1)*20+ks)*512+lane*16);
                    #pragma unroll
                    for(int nt=0;nt<8;++nt){
                        uint2 b=*(const uint2*)(bb+(ksl*32+ncg*8+nt)*256+lane*8);
                        mma16816(acc[nt],  a0,b);
                        mma16816(acc[8+nt],a1,b);
                    }
                }
                __syncthreads();
                if(c<3){
                    const char* s=(const char*)src+(c+2)*32768;
                    #pragma unroll
                    for(int i=0;i<4;++i)
                        cp16(sbB+(uint32_t)((c&1)*32768+(tid+NTH*i)*16), s+(tid+NTH*i)*16);
                    CP_COMMIT();
                }
            }
        }

        // ---- h epilogue: h=tanh(acc) -> A frags (hi/lo), h_final at t=15 ---
        #pragma unroll
        for(int mi=0;mi<2;++mi){
            int mt=2*mtp+mi;
            #pragma unroll
            for(int np=0;np<4;++np){
                float h[8];
                #pragma unroll
                for(int u=0;u<2;++u){
                    int nt=np*2+u;
                    h[u*4+0]=tanh_fast(acc[mi*8+nt][0]);
                    h[u*4+1]=tanh_fast(acc[mi*8+nt][1]);
                    h[u*4+2]=tanh_fast(acc[mi*8+nt][2]);
                    h[u*4+3]=tanh_fast(acc[mi*8+nt][3]);
                }
                uint4 hw,lw;
                split2(h[0],h[1],hw.x,lw.x); split2(h[2],h[3],hw.y,lw.y);
                split2(h[4],h[5],hw.z,lw.z); split2(h[6],h[7],hw.w,lw.w);
                int ks=4+ncg*4+np;
                uint32_t off=(uint32_t)((mt*20+ks)*512+lane*16);
                *(uint4*)(Ahi+off)=hw; *(uint4*)(Alo+off)=lw;
                if(t==T_STEPS-1){
                    int row=mt*16+(lane>>2), cb=ncg*64+np*16+(lane&3)*2;
                    float* hf=h_final+(size_t)(rowbase+row)*DH;
                    *(float2*)(hf+cb)            =make_float2(h[0],h[1]);
                    *(float2*)(hf+8*DH+cb)       =make_float2(h[2],h[3]);
                    *(float2*)(hf+cb+8)          =make_float2(h[4],h[5]);
                    *(float2*)(hf+8*DH+cb+8)     =make_float2(h[6],h[7]);
                }
            }
        }
        __syncthreads();

        // ---- h2o GEMM: D2[128x64] over K=256 (ks 4..19), 3 passes ----------
        {
            #pragma unroll
            for(int i=0;i<4;++i)
                cp16(sbB+(uint32_t)((tid+NTH*i)*16), (const char*)g_Ohi+(tid+NTH*i)*16);
            #pragma unroll
            for(int i=0;i<4;++i)
                cp16(sbB+(uint32_t)(32768+(tid+NTH*i)*16), (const char*)g_Olo+(tid+NTH*i)*16);
            CP_COMMIT(); CP_WAIT0(); __syncthreads();

            float a2[4][4];
            #pragma unroll
            for(int u=0;u<2;++u){
                int col=(ncg*2+u)*8+(lane&3)*2;
                float b0=cs[256+col], b1=cs[256+col+1];
                a2[u][0]=b0;a2[u][1]=b1;a2[u][2]=b0;a2[u][3]=b1;
                a2[2+u][0]=b0;a2[2+u][1]=b1;a2[2+u][2]=b0;a2[2+u][3]=b1;
            }
            #pragma unroll 1
            for(int p2=0;p2<3;++p2){
                const char* Ab=(p2<2)?Ahi:Alo;
                const char* Ob=Bb+((p2==1)?32768:0);
                #pragma unroll 1
                for(int ks2=0;ks2<16;++ks2){
                    uint4 a0=*(const uint4*)(Ab+((2*mtp  )*20+4+ks2)*512+lane*16);
                    uint4 a1=*(const uint4*)(Ab+((2*mtp+1)*20+4+ks2)*512+lane*16);
                    #pragma unroll
                    for(int u=0;u<2;++u){
                        uint2 b=*(const uint2*)(Ob+(ks2*8+ncg*2+u)*256+lane*8);
                        mma16816(a2[u],  a0,b);
                        mma16816(a2[2+u],a1,b);
                    }
                }
            }
            __syncthreads();
            // mid = tanh(D2) -> scratch [row][66]
            float* mid=(float*)(sm+OFF_MID);
            #pragma unroll
            for(int mi=0;mi<2;++mi){
                int row=(2*mtp+mi)*16+(lane>>2);
                #pragma unroll
                for(int u=0;u<2;++u){
                    int col=(ncg*2+u)*8+(lane&3)*2, idx=mi*2+u;
                    *(float2*)&mid[row*66+col]=
                        make_float2(tanh_fast(a2[idx][0]),tanh_fast(a2[idx][1]));
                    *(float2*)&mid[(row+8)*66+col]=
                        make_float2(tanh_fast(a2[idx][2]),tanh_fast(a2[idx][3]));
                }
            }
            __syncthreads();
            // fc
            {
                int row=tid>>2, o=tid&3;
                float s=cs[320+o];
                const float* wf=&cs[324+o*64];
                const float* mr=&mid[row*66];
                #pragma unroll
                for(int m=0;m<64;++m) s+=mr[m]*wf[m];
                out_seq[((size_t)t*BATCH+rowbase+row)*DOUT+o]=s;
            }
            __syncthreads();
        }
    }
}

// ----------------------------- launch wrapper -------------------------------
extern "C" void kernel_launch(void* const* d_in, const int* in_sizes, int n_in,
                              void* d_out, int out_size){
    const float* x     = (const float*)d_in[0];
    const float* hc1   = (const float*)d_in[1];
    const float* W_i2h = (const float*)d_in[2];
    const float* b_i2h = (const float*)d_in[3];
    const float* W_h2h = (const float*)d_in[4];
    const float* b_h2h = (const float*)d_in[5];
    const float* W_h2o = (const float*)d_in[6];
    const float* b_h2o = (const float*)d_in[7];
    const float* W_fc  = (const float*)d_in[8];
    const float* b_fc  = (const float*)d_in[9];

    float* out=(float*)d_out;
    float* h_final=out+(size_t)T_STEPS*BATCH*DOUT;

    prep<<<(256*320+64*256+255)/256, 256>>>(W_i2h, W_h2h, W_h2o);

    cudaFuncSetAttribute(rnn_mma, cudaFuncAttributeMaxDynamicSharedMemorySize,
                         SMEM_TOTAL);
    rnn_mma<<<BATCH/BT, NTH, SMEM_TOTAL>>>(
        x, hc1, b_i2h, b_h2h, b_h2o, W_fc, b_fc, out, h_final);
}